// round 3
// baseline (speedup 1.0000x reference)
#include <cuda_runtime.h>
#include <cuda_bf16.h>

#define TRUNC 2048
#define TLEN  2048
#define CAPV  200
#define RPB   4     // rows per block

// Precomputed per-channel tables of f(L), L in [0,200].
__device__ float g_tab[8][224];

// ---------------------------------------------------------------------------
// Kernel A: build the 8 x 201 transcendental tables (tiny).
// ---------------------------------------------------------------------------
__global__ void build_tab_kernel(const float* __restrict__ eta,
                                 const float* __restrict__ nu,
                                 const float* __restrict__ theta)
{
    int ch = blockIdx.x;
    int t  = threadIdx.x;
    if (t < 224) {
        float v = 0.0f;
        if (t <= CAPV) {
            float fl = (float)t;
            if (ch < 3) {
                float lam = tanhf(eta[ch]);
                float mag = powf(fabsf(lam), fl);
                v = ((t & 1) && lam < 0.0f) ? -mag : mag;
            } else if (ch < 6) {
                int h = ch - 3;
                float gam = 1.0f / (1.0f + expf(-nu[h]));
                float ang = theta[h] * fl;
                v = powf(gam, fl) * ((h == 2) ? sinf(ang) : cosf(ang));
            } else {
                int h = ch - 3;          // 3, 4
                float ang = theta[h] * fl;
                v = (h == 3) ? cosf(ang) : sinf(ang);
            }
        }
        g_tab[ch][t] = v;
    }
    __threadfence();
    cudaTriggerProgrammaticLaunchCompletion();
}

// ---------------------------------------------------------------------------
// Kernel B: region-structured fill, 4 rows per block.
// Phase 1 (no table needed): upper-triangle zeros + far-region constants.
//   far value per channel: ch0,1,3,4 -> 1 ; ch5,7 -> 0 ;
//   ch2 -> 1 at j%4==i%4 ; ch6 -> 1 at (i-j)%3==0.
// cudaGridDependencySynchronize()  (waits for build_tab under PDL)
// Phase 2: narrow diagonal bands via g_tab lookups.
// ---------------------------------------------------------------------------
__global__ __launch_bounds__(256)
void rem_fill_kernel(float* __restrict__ out)
{
    const int ch = blockIdx.y;
    const int i0 = blockIdx.x * RPB;
    const int t  = threadIdx.x;
    const float4 zero4 = make_float4(0.f, 0.f, 0.f, 0.f);

    int farth;                    // groups with jb < i - farth are "far"
    if      (ch == 2) farth = 806;
    else if (ch == 6) farth = 608;
    else              farth = 203;

    float4* __restrict__ base =
        (float4*)(out + ((size_t)ch * TRUNC + (size_t)i0) * TLEN);

    // ---- Phase 1: table-independent stores ----
    #pragma unroll
    for (int r = 0; r < RPB; r++) {
        const int i = i0 + r;
        float4* __restrict__ row4 = base + (size_t)r * (TLEN / 4);
        #pragma unroll
        for (int g = 0; g < 2; g++) {
            int q  = t + (g << 8);
            int jb = q << 2;
            if (jb > i) {
                __stcs(&row4[q], zero4);
            } else if (jb < i - farth) {
                float4 fv;
                if (ch == 2) {
                    int im = i & 3;
                    fv.x = (im == 0) ? 1.f : 0.f;
                    fv.y = (im == 1) ? 1.f : 0.f;
                    fv.z = (im == 2) ? 1.f : 0.f;
                    fv.w = (im == 3) ? 1.f : 0.f;
                } else if (ch == 6) {
                    unsigned r3 = (unsigned)(i - jb) % 3u;
                    fv.x = (r3 == 0u) ? 1.f : 0.f;
                    fv.y = (r3 == 1u) ? 1.f : 0.f;
                    fv.z = (r3 == 2u) ? 1.f : 0.f;
                    fv.w = (r3 == 0u) ? 1.f : 0.f;
                } else if (ch == 5 || ch == 7) {
                    fv = zero4;
                } else {
                    fv = make_float4(1.f, 1.f, 1.f, 1.f);
                }
                __stcs(&row4[q], fv);
            }
        }
    }

    // ---- wait for table (overlapped with phase 1 under PDL) ----
    cudaGridDependencySynchronize();
    const float* __restrict__ tab = g_tab[ch];

    // ---- Phase 2: diagonal bands ----
    #pragma unroll
    for (int r = 0; r < RPB; r++) {
        const int i = i0 + r;
        float4* __restrict__ row4 = base + (size_t)r * (TLEN / 4);
        #pragma unroll
        for (int g = 0; g < 2; g++) {
            int q  = t + (g << 8);
            int jb = q << 2;
            if (jb <= i && jb >= i - farth) {
                float4 rr;
                #pragma unroll
                for (int k = 0; k < 4; k++) {
                    int d = i - jb - k;
                    float v = 0.0f;
                    if (d >= 0) {
                        if (ch == 2) {
                            if ((d & 3) == 0) {
                                int dq = d >> 2;
                                v = __ldg(&tab[(dq > CAPV) ? 0 : dq]);
                            }
                        } else if (ch == 6) {
                            unsigned ud = (unsigned)d;
                            if (ud % 3u == 0u) {
                                unsigned dq = ud / 3u;
                                float a = __ldg(&tab[(dq > CAPV) ? 0 : (int)dq]);
                                float b = __ldg(&tab[(d  > CAPV) ? 0 : d]);
                                v = a * b;
                            }
                        } else if (ch == 7) {
                            if (d <= CAPV && (d & 1) == 0)
                                v = __ldg(&tab[d >> 1]) * __ldg(&tab[d]);
                        } else {
                            v = __ldg(&tab[(d > CAPV) ? 0 : d]);
                        }
                        if (d == 0) v -= 1.0f;
                    }
                    ((float*)&rr)[k] = v;
                }
                __stcs(&row4[q], rr);
            }
        }
    }
}

extern "C" void kernel_launch(void* const* d_in, const int* in_sizes, int n_in,
                              void* d_out, int out_size)
{
    const float* eta   = (const float*)d_in[0];
    const float* nu    = (const float*)d_in[1];
    const float* theta = (const float*)d_in[2];
    float* out = (float*)d_out;

    build_tab_kernel<<<8, 256>>>(eta, nu, theta);

    cudaLaunchConfig_t cfg = {};
    cfg.gridDim          = dim3(TRUNC / RPB, 8, 1);
    cfg.blockDim         = dim3(256, 1, 1);
    cfg.dynamicSmemBytes = 0;
    cfg.stream           = 0;
    cudaLaunchAttribute attr[1];
    attr[0].id = cudaLaunchAttributeProgrammaticStreamSerialization;
    attr[0].val.programmaticStreamSerializationAllowed = 1;
    cfg.attrs    = attr;
    cfg.numAttrs = 1;
    cudaLaunchKernelEx(&cfg, rem_fill_kernel, out);
}

// round 5
// speedup vs baseline: 1.0936x; 1.0936x over previous
#include <cuda_runtime.h>
#include <cuda_bf16.h>

#define TRUNC 2048
#define TLEN  2048
#define CAPV  200
#define RPB   4     // rows per block

// ---------------------------------------------------------------------------
// Single fused kernel. One block = (4 rows, 1 channel).
// Per block: build this channel's 201-entry f(L) table in SMEM (cheap:
// exp2f-based pow, MUFU sin/cos only 201x), then region-structured fill:
//   j > i                 -> 0
//   d = i-j > far_thresh  -> compile-time-constant pattern
//   else                  -> table lookups (narrow diagonal band)
// ---------------------------------------------------------------------------
__global__ __launch_bounds__(256)
void rem_kernel(const float* __restrict__ eta,
                const float* __restrict__ nu,
                const float* __restrict__ theta,
                float* __restrict__ out)
{
    __shared__ float tab[224];

    const int ch = blockIdx.y;
    const int i0 = blockIdx.x * RPB;
    const int t  = threadIdx.x;
    const float4 zero4 = make_float4(0.f, 0.f, 0.f, 0.f);

    // ---- build table (201 entries) with cheap math ----
    if (t <= CAPV) {
        float fl = (float)t;
        float v;
        if (ch < 3) {
            // ipow(tanh(eta), L) = sgn * exp2(L * log2|lam|)
            float lam = tanhf(eta[ch]);
            if (t == 0) {
                v = 1.0f;
            } else {
                float lg = __log2f(fabsf(lam));
                v = exp2f(fl * lg);
                if ((t & 1) && lam < 0.0f) v = -v;
            }
        } else if (ch < 6) {
            int h = ch - 3;
            float x = nu[h];
            // sigmoid(x)^L = exp2(-L * log2(1 + e^-x))
            float lg = -__log2f(1.0f + __expf(-x));   // log2(sigmoid)
            float mag = exp2f(fl * lg);
            float ang = theta[h] * fl;
            v = mag * ((h == 2) ? sinf(ang) : cosf(ang));
        } else {
            int h = ch - 3;          // 3, 4
            float ang = theta[h] * fl;
            v = (h == 3) ? cosf(ang) : sinf(ang);
        }
        tab[t] = v;
    }
    __syncthreads();

    int farth;                    // groups with jb < i - farth are "far"
    if      (ch == 2) farth = 806;
    else if (ch == 6) farth = 608;
    else              farth = 203;

    float4* __restrict__ base =
        (float4*)(out + ((size_t)ch * TRUNC + (size_t)i0) * TLEN);

    #pragma unroll
    for (int r = 0; r < RPB; r++) {
        const int i = i0 + r;
        float4* __restrict__ row4 = base + (size_t)r * (TLEN / 4);

        // far-region pattern for this (ch, i): independent of j except ch6
        float4 farv;
        if (ch == 2) {
            int im = i & 3;
            farv.x = (im == 0) ? 1.f : 0.f;
            farv.y = (im == 1) ? 1.f : 0.f;
            farv.z = (im == 2) ? 1.f : 0.f;
            farv.w = (im == 3) ? 1.f : 0.f;
        } else if (ch == 5 || ch == 7) {
            farv = zero4;
        } else {
            farv = make_float4(1.f, 1.f, 1.f, 1.f);
        }

        #pragma unroll
        for (int g = 0; g < 2; g++) {
            int q  = t + (g << 8);
            int jb = q << 2;
            float4 rr;
            if (jb > i) {
                rr = zero4;
            } else if (jb < i - farth) {
                if (ch == 6) {
                    unsigned r3 = (unsigned)(i - jb) % 3u;
                    rr.x = (r3 == 0u) ? 1.f : 0.f;
                    rr.y = (r3 == 1u) ? 1.f : 0.f;
                    rr.z = (r3 == 2u) ? 1.f : 0.f;
                    rr.w = (r3 == 0u) ? 1.f : 0.f;
                } else {
                    rr = farv;
                }
            } else {
                // diagonal band: table lookups
                #pragma unroll
                for (int k = 0; k < 4; k++) {
                    int d = i - jb - k;
                    float v = 0.0f;
                    if (d >= 0) {
                        if (ch == 2) {
                            if ((d & 3) == 0) {
                                int dq = d >> 2;
                                v = tab[(dq > CAPV) ? 0 : dq];
                            }
                        } else if (ch == 6) {
                            unsigned ud = (unsigned)d;
                            if (ud % 3u == 0u) {
                                unsigned dq = ud / 3u;
                                v = tab[(dq > CAPV) ? 0 : (int)dq]
                                  * tab[(d  > CAPV) ? 0 : d];
                            }
                        } else if (ch == 7) {
                            if (d <= CAPV && (d & 1) == 0)
                                v = tab[d >> 1] * tab[d];
                        } else {
                            v = tab[(d > CAPV) ? 0 : d];
                        }
                        if (d == 0) v -= 1.0f;
                    }
                    ((float*)&rr)[k] = v;
                }
            }
            __stcs(&row4[q], rr);
        }
    }
}

extern "C" void kernel_launch(void* const* d_in, const int* in_sizes, int n_in,
                              void* d_out, int out_size)
{
    const float* eta   = (const float*)d_in[0];
    const float* nu    = (const float*)d_in[1];
    const float* theta = (const float*)d_in[2];
    float* out = (float*)d_out;

    rem_kernel<<<dim3(TRUNC / RPB, 8), 256>>>(eta, nu, theta, out);
}